// round 4
// baseline (speedup 1.0000x reference)
#include <cuda_runtime.h>
#include <cstdint>

// Problem constants
#define NN      8192
#define CH      16
#define NQ      4               // k quarters (warp pairs)
#define QK      (NN / NQ)       // 2048 k per quarter
#define CK      128             // k staged per quarter per iteration
#define NIT     (QK / CK)       // 16 staging iterations
#define RS      (2 * CK + 4)    // 260 floats per (q,c2) shared row
#define BUF_FLOATS (NQ * 8 * RS)    // 8320 floats per buffer
#define SMEM_BYTES (2 * BUF_FLOATS * 4)  // 66560 B (double buffered)
#define THREADS 256
#define RPC     32              // rows per CTA
#define NCTA    (NN / RPC)      // 256

// Scratch (no allocation allowed): ping-pong xp buffers + accumulator
__device__ __align__(128) float g_xbuf0[NN * CH];
__device__ __align__(128) float g_xbuf1[NN * CH];
__device__ __align__(128) float g_acc[NN * CH];

// ---------------- packed f32x2 helpers ----------------
__device__ __forceinline__ unsigned long long f2_fma(unsigned long long a,
                                                     unsigned long long b,
                                                     unsigned long long c) {
    unsigned long long d;
    asm("fma.rn.f32x2 %0, %1, %2, %3;" : "=l"(d) : "l"(a), "l"(b), "l"(c));
    return d;
}
__device__ __forceinline__ unsigned long long f2_add(unsigned long long a,
                                                     unsigned long long b) {
    unsigned long long d;
    asm("add.rn.f32x2 %0, %1, %2;" : "=l"(d) : "l"(a), "l"(b));
    return d;
}
__device__ __forceinline__ unsigned long long f2_pack(float lo, float hi) {
    unsigned long long d;
    asm("mov.b64 %0, {%1, %2};" : "=l"(d) : "f"(lo), "f"(hi));
    return d;
}
__device__ __forceinline__ void f2_unpack(unsigned long long v, float& lo, float& hi) {
    asm("mov.b64 {%0, %1}, %2;" : "=f"(lo), "=f"(hi) : "l"(v));
}

// ---------------- kernel 0: acc = relu(x @ W0) ----------------
__global__ void k_init(const float* __restrict__ x,
                       const float* __restrict__ W,   // W0: [16][16]
                       float* __restrict__ acc) {
    __shared__ float sW[CH * CH];
    int t = threadIdx.x;
    sW[t] = W[t];
    __syncthreads();

    int row = blockIdx.x * blockDim.x + t;
    const float4* xr4 = reinterpret_cast<const float4*>(x + (size_t)row * CH);
    float xr[CH];
    float4 v0 = xr4[0], v1 = xr4[1], v2 = xr4[2], v3 = xr4[3];
    xr[0]=v0.x; xr[1]=v0.y; xr[2]=v0.z; xr[3]=v0.w;
    xr[4]=v1.x; xr[5]=v1.y; xr[6]=v1.z; xr[7]=v1.w;
    xr[8]=v2.x; xr[9]=v2.y; xr[10]=v2.z; xr[11]=v2.w;
    xr[12]=v3.x; xr[13]=v3.y; xr[14]=v3.z; xr[15]=v3.w;

    float o[CH];
    #pragma unroll
    for (int c = 0; c < CH; c++) o[c] = 0.f;
    #pragma unroll
    for (int j = 0; j < CH; j++) {
        #pragma unroll
        for (int c = 0; c < CH; c++) o[c] += xr[j] * sW[j * CH + c];
    }
    float* ar = acc + (size_t)row * CH;
    #pragma unroll
    for (int c = 0; c < CH; c++) ar[c] = fmaxf(o[c], 0.f);
}

// ---------------- pass kernel ----------------
// Warp layout: warp = rowset s (0..1, 16 rows each) x k-quarter q (0..3).
// Lane = group g (0..3, 4 rows each) * 8 + j (k stride within quarter).
// Shared xp chunk (per buffer): sxp[q][c2][2*kk + e]  (pair-major per channel pair)
template <bool FINAL>
__global__ __launch_bounds__(THREADS, 2)
void k_pass(const float* __restrict__ L,
            const float* __restrict__ xin,
            float* __restrict__ xout,
            const float* __restrict__ W,      // Wp: [16][16]
            float* __restrict__ acc,
            float* __restrict__ outp) {
    extern __shared__ float smem[];           // 2 * BUF_FLOATS
    __shared__ float sW[CH * CH];

    int t = threadIdx.x;
    sW[t] = W[t];

    int warp = t >> 5;
    int lane = t & 31;
    int q = warp >> 1;          // k-quarter
    int s = warp & 1;           // rowset
    int g = lane >> 3;          // row group
    int j = lane & 7;           // k lane within group

    int ctarow = blockIdx.x * RPC;
    int myrow0 = ctarow + s * 16 + g * 4;            // first of 4 rows for this lane
    const float* Lbase = L + (size_t)myrow0 * NN + q * QK;

    // staging mapping: thread t stages k-rows klocal = t and t+256 of each iter
    int q1 = t >> 7, kk1 = t & 127;
    const float4* xin4 = reinterpret_cast<const float4*>(xin);

    unsigned long long a2[4][8];
    #pragma unroll
    for (int r = 0; r < 4; r++)
        #pragma unroll
        for (int c2 = 0; c2 < 8; c2++) a2[r][c2] = 0ull;

    // ---- prologue: stage iter 0 into buffer 0 ----
    {
        float* nbuf = smem;
        const float4* p = xin4 + ((size_t)q1 * QK + kk1) * 4;
        float4 A0 = p[0], A1 = p[1], A2 = p[2], A3 = p[3];
        const float4* p2 = xin4 + ((size_t)(q1 + 2) * QK + kk1) * 4;
        float4 B0 = p2[0], B1 = p2[1], B2 = p2[2], B3 = p2[3];
        float* d1 = nbuf + q1 * 8 * RS + 2 * kk1;
        *(float2*)(d1 + 0*RS) = make_float2(A0.x, A0.y);
        *(float2*)(d1 + 1*RS) = make_float2(A0.z, A0.w);
        *(float2*)(d1 + 2*RS) = make_float2(A1.x, A1.y);
        *(float2*)(d1 + 3*RS) = make_float2(A1.z, A1.w);
        *(float2*)(d1 + 4*RS) = make_float2(A2.x, A2.y);
        *(float2*)(d1 + 5*RS) = make_float2(A2.z, A2.w);
        *(float2*)(d1 + 6*RS) = make_float2(A3.x, A3.y);
        *(float2*)(d1 + 7*RS) = make_float2(A3.z, A3.w);
        float* d2 = nbuf + (q1 + 2) * 8 * RS + 2 * kk1;
        *(float2*)(d2 + 0*RS) = make_float2(B0.x, B0.y);
        *(float2*)(d2 + 1*RS) = make_float2(B0.z, B0.w);
        *(float2*)(d2 + 2*RS) = make_float2(B1.x, B1.y);
        *(float2*)(d2 + 3*RS) = make_float2(B1.z, B1.w);
        *(float2*)(d2 + 4*RS) = make_float2(B2.x, B2.y);
        *(float2*)(d2 + 5*RS) = make_float2(B2.z, B2.w);
        *(float2*)(d2 + 6*RS) = make_float2(B3.x, B3.y);
        *(float2*)(d2 + 7*RS) = make_float2(B3.z, B3.w);
    }

    // ---- L software pipeline: preload m = 0 ----
    float2 lv0, lv1, lv2, lv3;
    {
        int koff = 2 * j;
        lv0 = *(const float2*)(Lbase + 0 * NN + koff);
        lv1 = *(const float2*)(Lbase + 1 * NN + koff);
        lv2 = *(const float2*)(Lbase + 2 * NN + koff);
        lv3 = *(const float2*)(Lbase + 3 * NN + koff);
    }

    __syncthreads();

    // inner compute step for global k-step m (= i*8 + it)
    #define INNER(m_cur, cbuf)                                                      \
    {                                                                               \
        unsigned long long x0 = f2_pack(lv0.x, lv0.x), y0 = f2_pack(lv0.y, lv0.y);  \
        unsigned long long x1 = f2_pack(lv1.x, lv1.x), y1 = f2_pack(lv1.y, lv1.y);  \
        unsigned long long x2 = f2_pack(lv2.x, lv2.x), y2 = f2_pack(lv2.y, lv2.y);  \
        unsigned long long x3 = f2_pack(lv3.x, lv3.x), y3 = f2_pack(lv3.y, lv3.y);  \
        int mn = (m_cur) + 1; if (mn > 8 * NIT - 1) mn = 8 * NIT - 1;               \
        int koffn = (mn >> 3) * CK + (mn & 7) * 16 + 2 * j;                         \
        lv0 = *(const float2*)(Lbase + 0 * NN + koffn);                             \
        lv1 = *(const float2*)(Lbase + 1 * NN + koffn);                             \
        lv2 = *(const float2*)(Lbase + 2 * NN + koffn);                             \
        lv3 = *(const float2*)(Lbase + 3 * NN + koffn);                             \
        const float* bp = (cbuf) + q * 8 * RS + 2 * (((m_cur) & 7) * 16 + 2 * j);   \
        _Pragma("unroll")                                                           \
        for (int c2 = 0; c2 < 8; c2++) {                                            \
            ulonglong2 qv = *(const ulonglong2*)(bp + c2 * RS);                     \
            a2[0][c2] = f2_fma(x0, qv.x, a2[0][c2]);                                \
            a2[0][c2] = f2_fma(y0, qv.y, a2[0][c2]);                                \
            a2[1][c2] = f2_fma(x1, qv.x, a2[1][c2]);                                \
            a2[1][c2] = f2_fma(y1, qv.y, a2[1][c2]);                                \
            a2[2][c2] = f2_fma(x2, qv.x, a2[2][c2]);                                \
            a2[2][c2] = f2_fma(y2, qv.y, a2[2][c2]);                                \
            a2[3][c2] = f2_fma(x3, qv.x, a2[3][c2]);                                \
            a2[3][c2] = f2_fma(y3, qv.y, a2[3][c2]);                                \
        }                                                                           \
    }

    for (int i = 0; i < NIT; i++) {
        float* cbuf = smem + (i & 1) * BUF_FLOATS;
        float* nbuf = smem + ((i + 1) & 1) * BUF_FLOATS;
        bool more = (i + 1 < NIT);
        int m0 = i * 8;

        // issue staged loads for iter i+1 (first k row), then compute its 0..3
        float4 A0, A1, A2, A3;
        if (more) {
            const float4* p = xin4 + ((size_t)q1 * QK + (i + 1) * CK + kk1) * 4;
            A0 = p[0]; A1 = p[1]; A2 = p[2]; A3 = p[3];
        }
        INNER(m0 + 0, cbuf) INNER(m0 + 1, cbuf) INNER(m0 + 2, cbuf) INNER(m0 + 3, cbuf)

        float4 B0, B1, B2, B3;
        if (more) {
            float* d1 = nbuf + q1 * 8 * RS + 2 * kk1;
            *(float2*)(d1 + 0*RS) = make_float2(A0.x, A0.y);
            *(float2*)(d1 + 1*RS) = make_float2(A0.z, A0.w);
            *(float2*)(d1 + 2*RS) = make_float2(A1.x, A1.y);
            *(float2*)(d1 + 3*RS) = make_float2(A1.z, A1.w);
            *(float2*)(d1 + 4*RS) = make_float2(A2.x, A2.y);
            *(float2*)(d1 + 5*RS) = make_float2(A2.z, A2.w);
            *(float2*)(d1 + 6*RS) = make_float2(A3.x, A3.y);
            *(float2*)(d1 + 7*RS) = make_float2(A3.z, A3.w);
            const float4* p2 = xin4 + ((size_t)(q1 + 2) * QK + (i + 1) * CK + kk1) * 4;
            B0 = p2[0]; B1 = p2[1]; B2 = p2[2]; B3 = p2[3];
        }
        INNER(m0 + 4, cbuf) INNER(m0 + 5, cbuf) INNER(m0 + 6, cbuf) INNER(m0 + 7, cbuf)

        if (more) {
            float* d2 = nbuf + (q1 + 2) * 8 * RS + 2 * kk1;
            *(float2*)(d2 + 0*RS) = make_float2(B0.x, B0.y);
            *(float2*)(d2 + 1*RS) = make_float2(B0.z, B0.w);
            *(float2*)(d2 + 2*RS) = make_float2(B1.x, B1.y);
            *(float2*)(d2 + 3*RS) = make_float2(B1.z, B1.w);
            *(float2*)(d2 + 4*RS) = make_float2(B2.x, B2.y);
            *(float2*)(d2 + 5*RS) = make_float2(B2.z, B2.w);
            *(float2*)(d2 + 6*RS) = make_float2(B3.x, B3.y);
            *(float2*)(d2 + 7*RS) = make_float2(B3.z, B3.w);
        }
        __syncthreads();
    }
    #undef INNER

    // ---- reduce over j lanes (xor on low 3 bits of lane id) ----
    float y[4][CH];
    #pragma unroll
    for (int r = 0; r < 4; r++) {
        #pragma unroll
        for (int c2 = 0; c2 < 8; c2++) {
            unsigned long long v = a2[r][c2];
            v = f2_add(v, __shfl_xor_sync(0xffffffffu, v, 1, 32));
            v = f2_add(v, __shfl_xor_sync(0xffffffffu, v, 2, 32));
            v = f2_add(v, __shfl_xor_sync(0xffffffffu, v, 4, 32));
            f2_unpack(v, y[r][2 * c2], y[r][2 * c2 + 1]);
        }
    }

    // ---- cross-quarter reduction through shared (reuse buffer 0) ----
    // red[(s*NQ + q)*256 + rloc*16 + ch]
    float* red = smem;
    #pragma unroll
    for (int u = 0; u < 8; u++) {
        int e = u * 8 + j;            // 0..63
        int r = e >> 4, c = e & 15;
        red[(s * NQ + q) * 256 + (g * 4 + r) * 16 + c] = y[r][c];
    }
    __syncthreads();

    float* redsum = smem + 2 * NQ * 256;   // 512 floats
    #pragma unroll
    for (int h = 0; h < 2; h++) {
        int v = t + h * 256;               // v = row*16 + ch, row 0..31
        int srow = v >> 8;
        int rest = v & 255;
        float ys = red[(srow * NQ + 0) * 256 + rest]
                 + red[(srow * NQ + 1) * 256 + rest]
                 + red[(srow * NQ + 2) * 256 + rest]
                 + red[(srow * NQ + 3) * 256 + rest];
        redsum[v] = ys;
        if (!FINAL) {
            int row = v >> 4, c = v & 15;
            xout[(size_t)(ctarow + row) * CH + c] = ys;   // raw L^p x
        }
    }
    __syncthreads();

    // ---- tiny GEMM with Wp + relu + accumulate ----
    #pragma unroll
    for (int h = 0; h < 2; h++) {
        int o = t + h * 256;
        int row = o >> 4, c = o & 15;
        float sv = 0.f;
        #pragma unroll
        for (int jj = 0; jj < CH; jj++) sv += redsum[row * 16 + jj] * sW[jj * CH + c];
        sv = fmaxf(sv, 0.f);
        size_t gi = (size_t)(ctarow + row) * CH + c;
        if (!FINAL) {
            acc[gi] += sv;
        } else {
            outp[gi] = fmaxf(acc[gi] + sv, 0.f);
        }
    }
}

extern "C" void kernel_launch(void* const* d_in, const int* in_sizes, int n_in,
                              void* d_out, int out_size) {
    const float* x = (const float*)d_in[0];   // [8192, 16]
    const float* L = (const float*)d_in[1];   // [8192, 8192]
    const float* W = (const float*)d_in[2];   // [5, 16, 16]
    float* out = (float*)d_out;

    void *p0, *p1, *pa;
    cudaGetSymbolAddress(&p0, g_xbuf0);
    cudaGetSymbolAddress(&p1, g_xbuf1);
    cudaGetSymbolAddress(&pa, g_acc);
    float* xb0 = (float*)p0;
    float* xb1 = (float*)p1;
    float* acc = (float*)pa;

    cudaFuncSetAttribute(k_pass<false>, cudaFuncAttributeMaxDynamicSharedMemorySize, SMEM_BYTES);
    cudaFuncSetAttribute(k_pass<true>,  cudaFuncAttributeMaxDynamicSharedMemorySize, SMEM_BYTES);

    k_init<<<NN / THREADS, THREADS>>>(x, W, acc);                                        // acc = relu(x@W0)
    k_pass<false><<<NCTA, THREADS, SMEM_BYTES>>>(L, x,   xb0, W + 1 * 256, acc, nullptr); // p=1
    k_pass<false><<<NCTA, THREADS, SMEM_BYTES>>>(L, xb0, xb1, W + 2 * 256, acc, nullptr); // p=2
    k_pass<false><<<NCTA, THREADS, SMEM_BYTES>>>(L, xb1, xb0, W + 3 * 256, acc, nullptr); // p=3
    k_pass<true ><<<NCTA, THREADS, SMEM_BYTES>>>(L, xb0, nullptr, W + 4 * 256, acc, out); // p=4
}

// round 5
// speedup vs baseline: 1.0015x; 1.0015x over previous
#include <cuda_runtime.h>
#include <cstdint>

// Problem constants
#define NN      8192
#define CH      16
#define NQ      4               // k quarters (warp pairs)
#define QK      (NN / NQ)       // 2048 k per quarter
#define CK      128             // k staged per quarter per iteration
#define NIT     (QK / CK)       // 16 staging iterations
#define RS      (2 * CK + 4)    // 260 floats per (q,c2) shared row
#define BUF_FLOATS (NQ * 8 * RS)    // 8320 floats per buffer
#define SMEM_BYTES (2 * BUF_FLOATS * 4)  // 66560 B (double buffered)
#define THREADS 256
#define RPC     32              // rows per CTA
#define NCTA    (NN / RPC)      // 256

// Scratch (no allocation allowed): ping-pong xp buffers + accumulator
__device__ __align__(128) float g_xbuf0[NN * CH];
__device__ __align__(128) float g_xbuf1[NN * CH];
__device__ __align__(128) float g_acc[NN * CH];

// ---------------- packed f32x2 helpers ----------------
__device__ __forceinline__ unsigned long long f2_fma(unsigned long long a,
                                                     unsigned long long b,
                                                     unsigned long long c) {
    unsigned long long d;
    asm("fma.rn.f32x2 %0, %1, %2, %3;" : "=l"(d) : "l"(a), "l"(b), "l"(c));
    return d;
}
__device__ __forceinline__ unsigned long long f2_add(unsigned long long a,
                                                     unsigned long long b) {
    unsigned long long d;
    asm("add.rn.f32x2 %0, %1, %2;" : "=l"(d) : "l"(a), "l"(b));
    return d;
}
__device__ __forceinline__ unsigned long long f2_pack(float lo, float hi) {
    unsigned long long d;
    asm("mov.b64 %0, {%1, %2};" : "=l"(d) : "f"(lo), "f"(hi));
    return d;
}
__device__ __forceinline__ void f2_unpack(unsigned long long v, float& lo, float& hi) {
    asm("mov.b64 {%0, %1}, %2;" : "=f"(lo), "=f"(hi) : "l"(v));
}

// ---------------- kernel 0: acc = relu(x @ W0) ----------------
__global__ void k_init(const float* __restrict__ x,
                       const float* __restrict__ W,   // W0: [16][16]
                       float* __restrict__ acc) {
    __shared__ float sW[CH * CH];
    int t = threadIdx.x;
    sW[t] = W[t];
    __syncthreads();

    int row = blockIdx.x * blockDim.x + t;
    const float4* xr4 = reinterpret_cast<const float4*>(x + (size_t)row * CH);
    float xr[CH];
    float4 v0 = xr4[0], v1 = xr4[1], v2 = xr4[2], v3 = xr4[3];
    xr[0]=v0.x; xr[1]=v0.y; xr[2]=v0.z; xr[3]=v0.w;
    xr[4]=v1.x; xr[5]=v1.y; xr[6]=v1.z; xr[7]=v1.w;
    xr[8]=v2.x; xr[9]=v2.y; xr[10]=v2.z; xr[11]=v2.w;
    xr[12]=v3.x; xr[13]=v3.y; xr[14]=v3.z; xr[15]=v3.w;

    float o[CH];
    #pragma unroll
    for (int c = 0; c < CH; c++) o[c] = 0.f;
    #pragma unroll
    for (int j = 0; j < CH; j++) {
        #pragma unroll
        for (int c = 0; c < CH; c++) o[c] += xr[j] * sW[j * CH + c];
    }
    float* ar = acc + (size_t)row * CH;
    #pragma unroll
    for (int c = 0; c < CH; c++) ar[c] = fmaxf(o[c], 0.f);
}

// ---------------- pass kernel ----------------
// Warp layout: warp = rowset s (0..1, 16 rows each) x k-quarter q (0..3).
// Lane = group g (0..3, 4 rows each) * 8 + j (k stride within quarter).
// Shared xp chunk (per buffer): sxp[q][c2][2*kk + e]  (pair-major per channel pair)
template <bool FINAL>
__global__ __launch_bounds__(THREADS, 2)
void k_pass(const float* __restrict__ L,
            const float* __restrict__ xin,
            float* __restrict__ xout,
            const float* __restrict__ W,      // Wp: [16][16]
            float* __restrict__ acc,
            float* __restrict__ outp) {
    extern __shared__ float smem[];           // 2 * BUF_FLOATS
    __shared__ float sW[CH * CH];

    int t = threadIdx.x;
    sW[t] = W[t];

    int warp = t >> 5;
    int lane = t & 31;
    int q = warp >> 1;          // k-quarter
    int s = warp & 1;           // rowset
    int g = lane >> 3;          // row group
    int j = lane & 7;           // k lane within group

    int ctarow = blockIdx.x * RPC;
    int myrow0 = ctarow + s * 16 + g * 4;            // first of 4 rows for this lane
    const float* Lbase = L + (size_t)myrow0 * NN + q * QK;

    // staging mapping: thread t stages k-rows klocal = t and t+256 of each iter
    int q1 = t >> 7, kk1 = t & 127;
    const float4* xin4 = reinterpret_cast<const float4*>(xin);

    unsigned long long a2[4][8];
    #pragma unroll
    for (int r = 0; r < 4; r++)
        #pragma unroll
        for (int c2 = 0; c2 < 8; c2++) a2[r][c2] = 0ull;

    // ---- prologue: stage iter 0 into buffer 0 ----
    {
        float* nbuf = smem;
        const float4* p = xin4 + ((size_t)q1 * QK + kk1) * 4;
        float4 A0 = p[0], A1 = p[1], A2 = p[2], A3 = p[3];
        const float4* p2 = xin4 + ((size_t)(q1 + 2) * QK + kk1) * 4;
        float4 B0 = p2[0], B1 = p2[1], B2 = p2[2], B3 = p2[3];
        float* d1 = nbuf + q1 * 8 * RS + 2 * kk1;
        *(float2*)(d1 + 0*RS) = make_float2(A0.x, A0.y);
        *(float2*)(d1 + 1*RS) = make_float2(A0.z, A0.w);
        *(float2*)(d1 + 2*RS) = make_float2(A1.x, A1.y);
        *(float2*)(d1 + 3*RS) = make_float2(A1.z, A1.w);
        *(float2*)(d1 + 4*RS) = make_float2(A2.x, A2.y);
        *(float2*)(d1 + 5*RS) = make_float2(A2.z, A2.w);
        *(float2*)(d1 + 6*RS) = make_float2(A3.x, A3.y);
        *(float2*)(d1 + 7*RS) = make_float2(A3.z, A3.w);
        float* d2 = nbuf + (q1 + 2) * 8 * RS + 2 * kk1;
        *(float2*)(d2 + 0*RS) = make_float2(B0.x, B0.y);
        *(float2*)(d2 + 1*RS) = make_float2(B0.z, B0.w);
        *(float2*)(d2 + 2*RS) = make_float2(B1.x, B1.y);
        *(float2*)(d2 + 3*RS) = make_float2(B1.z, B1.w);
        *(float2*)(d2 + 4*RS) = make_float2(B2.x, B2.y);
        *(float2*)(d2 + 5*RS) = make_float2(B2.z, B2.w);
        *(float2*)(d2 + 6*RS) = make_float2(B3.x, B3.y);
        *(float2*)(d2 + 7*RS) = make_float2(B3.z, B3.w);
    }

    // ---- L software pipeline: preload m = 0 ----
    float2 lv0, lv1, lv2, lv3;
    {
        int koff = 2 * j;
        lv0 = *(const float2*)(Lbase + 0 * NN + koff);
        lv1 = *(const float2*)(Lbase + 1 * NN + koff);
        lv2 = *(const float2*)(Lbase + 2 * NN + koff);
        lv3 = *(const float2*)(Lbase + 3 * NN + koff);
    }

    __syncthreads();

    // inner compute step for global k-step m (= i*8 + it)
    #define INNER(m_cur, cbuf)                                                      \
    {                                                                               \
        unsigned long long x0 = f2_pack(lv0.x, lv0.x), y0 = f2_pack(lv0.y, lv0.y);  \
        unsigned long long x1 = f2_pack(lv1.x, lv1.x), y1 = f2_pack(lv1.y, lv1.y);  \
        unsigned long long x2 = f2_pack(lv2.x, lv2.x), y2 = f2_pack(lv2.y, lv2.y);  \
        unsigned long long x3 = f2_pack(lv3.x, lv3.x), y3 = f2_pack(lv3.y, lv3.y);  \
        int mn = (m_cur) + 1; if (mn > 8 * NIT - 1) mn = 8 * NIT - 1;               \
        int koffn = (mn >> 3) * CK + (mn & 7) * 16 + 2 * j;                         \
        lv0 = *(const float2*)(Lbase + 0 * NN + koffn);                             \
        lv1 = *(const float2*)(Lbase + 1 * NN + koffn);                             \
        lv2 = *(const float2*)(Lbase + 2 * NN + koffn);                             \
        lv3 = *(const float2*)(Lbase + 3 * NN + koffn);                             \
        const float* bp = (cbuf) + q * 8 * RS + 2 * (((m_cur) & 7) * 16 + 2 * j);   \
        _Pragma("unroll")                                                           \
        for (int c2 = 0; c2 < 8; c2++) {                                            \
            ulonglong2 qv = *(const ulonglong2*)(bp + c2 * RS);                     \
            a2[0][c2] = f2_fma(x0, qv.x, a2[0][c2]);                                \
            a2[0][c2] = f2_fma(y0, qv.y, a2[0][c2]);                                \
            a2[1][c2] = f2_fma(x1, qv.x, a2[1][c2]);                                \
            a2[1][c2] = f2_fma(y1, qv.y, a2[1][c2]);                                \
            a2[2][c2] = f2_fma(x2, qv.x, a2[2][c2]);                                \
            a2[2][c2] = f2_fma(y2, qv.y, a2[2][c2]);                                \
            a2[3][c2] = f2_fma(x3, qv.x, a2[3][c2]);                                \
            a2[3][c2] = f2_fma(y3, qv.y, a2[3][c2]);                                \
        }                                                                           \
    }

    for (int i = 0; i < NIT; i++) {
        float* cbuf = smem + (i & 1) * BUF_FLOATS;
        float* nbuf = smem + ((i + 1) & 1) * BUF_FLOATS;
        bool more = (i + 1 < NIT);
        int m0 = i * 8;

        // issue staged loads for iter i+1 (first k row), then compute its 0..3
        float4 A0, A1, A2, A3;
        if (more) {
            const float4* p = xin4 + ((size_t)q1 * QK + (i + 1) * CK + kk1) * 4;
            A0 = p[0]; A1 = p[1]; A2 = p[2]; A3 = p[3];
        }
        INNER(m0 + 0, cbuf) INNER(m0 + 1, cbuf) INNER(m0 + 2, cbuf) INNER(m0 + 3, cbuf)

        float4 B0, B1, B2, B3;
        if (more) {
            float* d1 = nbuf + q1 * 8 * RS + 2 * kk1;
            *(float2*)(d1 + 0*RS) = make_float2(A0.x, A0.y);
            *(float2*)(d1 + 1*RS) = make_float2(A0.z, A0.w);
            *(float2*)(d1 + 2*RS) = make_float2(A1.x, A1.y);
            *(float2*)(d1 + 3*RS) = make_float2(A1.z, A1.w);
            *(float2*)(d1 + 4*RS) = make_float2(A2.x, A2.y);
            *(float2*)(d1 + 5*RS) = make_float2(A2.z, A2.w);
            *(float2*)(d1 + 6*RS) = make_float2(A3.x, A3.y);
            *(float2*)(d1 + 7*RS) = make_float2(A3.z, A3.w);
            const float4* p2 = xin4 + ((size_t)(q1 + 2) * QK + (i + 1) * CK + kk1) * 4;
            B0 = p2[0]; B1 = p2[1]; B2 = p2[2]; B3 = p2[3];
        }
        INNER(m0 + 4, cbuf) INNER(m0 + 5, cbuf) INNER(m0 + 6, cbuf) INNER(m0 + 7, cbuf)

        if (more) {
            float* d2 = nbuf + (q1 + 2) * 8 * RS + 2 * kk1;
            *(float2*)(d2 + 0*RS) = make_float2(B0.x, B0.y);
            *(float2*)(d2 + 1*RS) = make_float2(B0.z, B0.w);
            *(float2*)(d2 + 2*RS) = make_float2(B1.x, B1.y);
            *(float2*)(d2 + 3*RS) = make_float2(B1.z, B1.w);
            *(float2*)(d2 + 4*RS) = make_float2(B2.x, B2.y);
            *(float2*)(d2 + 5*RS) = make_float2(B2.z, B2.w);
            *(float2*)(d2 + 6*RS) = make_float2(B3.x, B3.y);
            *(float2*)(d2 + 7*RS) = make_float2(B3.z, B3.w);
        }
        __syncthreads();
    }
    #undef INNER

    // ---- reduce over j lanes (xor on low 3 bits of lane id) ----
    float y[4][CH];
    #pragma unroll
    for (int r = 0; r < 4; r++) {
        #pragma unroll
        for (int c2 = 0; c2 < 8; c2++) {
            unsigned long long v = a2[r][c2];
            v = f2_add(v, __shfl_xor_sync(0xffffffffu, v, 1, 32));
            v = f2_add(v, __shfl_xor_sync(0xffffffffu, v, 2, 32));
            v = f2_add(v, __shfl_xor_sync(0xffffffffu, v, 4, 32));
            f2_unpack(v, y[r][2 * c2], y[r][2 * c2 + 1]);
        }
    }

    // ---- cross-quarter reduction through shared (reuse buffer 0) ----
    // red[(s*NQ + q)*256 + rloc*16 + ch]
    float* red = smem;
    #pragma unroll
    for (int u = 0; u < 8; u++) {
        int e = u * 8 + j;            // 0..63
        int r = e >> 4, c = e & 15;
        red[(s * NQ + q) * 256 + (g * 4 + r) * 16 + c] = y[r][c];
    }
    __syncthreads();

    float* redsum = smem + 2 * NQ * 256;   // 512 floats
    #pragma unroll
    for (int h = 0; h < 2; h++) {
        int v = t + h * 256;               // v = row*16 + ch, row 0..31
        int srow = v >> 8;
        int rest = v & 255;
        float ys = red[(srow * NQ + 0) * 256 + rest]
                 + red[(srow * NQ + 1) * 256 + rest]
                 + red[(srow * NQ + 2) * 256 + rest]
                 + red[(srow * NQ + 3) * 256 + rest];
        redsum[v] = ys;
        if (!FINAL) {
            int row = v >> 4, c = v & 15;
            xout[(size_t)(ctarow + row) * CH + c] = ys;   // raw L^p x
        }
    }
    __syncthreads();

    // ---- tiny GEMM with Wp + relu + accumulate ----
    #pragma unroll
    for (int h = 0; h < 2; h++) {
        int o = t + h * 256;
        int row = o >> 4, c = o & 15;
        float sv = 0.f;
        #pragma unroll
        for (int jj = 0; jj < CH; jj++) sv += redsum[row * 16 + jj] * sW[jj * CH + c];
        sv = fmaxf(sv, 0.f);
        size_t gi = (size_t)(ctarow + row) * CH + c;
        if (!FINAL) {
            acc[gi] += sv;
        } else {
            outp[gi] = fmaxf(acc[gi] + sv, 0.f);
        }
    }
}

extern "C" void kernel_launch(void* const* d_in, const int* in_sizes, int n_in,
                              void* d_out, int out_size) {
    const float* x = (const float*)d_in[0];   // [8192, 16]
    const float* L = (const float*)d_in[1];   // [8192, 8192]
    const float* W = (const float*)d_in[2];   // [5, 16, 16]
    float* out = (float*)d_out;

    void *p0, *p1, *pa;
    cudaGetSymbolAddress(&p0, g_xbuf0);
    cudaGetSymbolAddress(&p1, g_xbuf1);
    cudaGetSymbolAddress(&pa, g_acc);
    float* xb0 = (float*)p0;
    float* xb1 = (float*)p1;
    float* acc = (float*)pa;

    cudaFuncSetAttribute(k_pass<false>, cudaFuncAttributeMaxDynamicSharedMemorySize, SMEM_BYTES);
    cudaFuncSetAttribute(k_pass<true>,  cudaFuncAttributeMaxDynamicSharedMemorySize, SMEM_BYTES);

    k_init<<<NN / THREADS, THREADS>>>(x, W, acc);                                        // acc = relu(x@W0)
    k_pass<false><<<NCTA, THREADS, SMEM_BYTES>>>(L, x,   xb0, W + 1 * 256, acc, nullptr); // p=1
    k_pass<false><<<NCTA, THREADS, SMEM_BYTES>>>(L, xb0, xb1, W + 2 * 256, acc, nullptr); // p=2
    k_pass<false><<<NCTA, THREADS, SMEM_BYTES>>>(L, xb1, xb0, W + 3 * 256, acc, nullptr); // p=3
    k_pass<true ><<<NCTA, THREADS, SMEM_BYTES>>>(L, xb0, nullptr, W + 4 * 256, acc, out); // p=4
}

// round 6
// speedup vs baseline: 1.0176x; 1.0161x over previous
#include <cuda_runtime.h>
#include <cstdint>

// Problem constants
#define NN      8192
#define CH      16
#define KT      256            // k staged per half per iteration
#define NIT     16             // staging iterations (16 * 256 * 2 halves = 8192)
#define RS      (2 * KT + 4)   // 516 floats per (q,c2) shared row (16B-aligned, bank-staggered)
#define THREADS 128
#define RPC     16             // rows per CTA
#define NCTA    (NN / RPC)     // 512

// Scratch (no allocation allowed): ping-pong xp buffers + accumulator
__device__ __align__(128) float g_xbuf0[NN * CH];
__device__ __align__(128) float g_xbuf1[NN * CH];
__device__ __align__(128) float g_acc[NN * CH];

// ---------------- packed f32x2 helpers ----------------
__device__ __forceinline__ unsigned long long f2_fma(unsigned long long a,
                                                     unsigned long long b,
                                                     unsigned long long c) {
    unsigned long long d;
    asm("fma.rn.f32x2 %0, %1, %2, %3;" : "=l"(d) : "l"(a), "l"(b), "l"(c));
    return d;
}
__device__ __forceinline__ unsigned long long f2_add(unsigned long long a,
                                                     unsigned long long b) {
    unsigned long long d;
    asm("add.rn.f32x2 %0, %1, %2;" : "=l"(d) : "l"(a), "l"(b));
    return d;
}
__device__ __forceinline__ unsigned long long f2_pack(float lo, float hi) {
    unsigned long long d;
    asm("mov.b64 %0, {%1, %2};" : "=l"(d) : "f"(lo), "f"(hi));
    return d;
}
__device__ __forceinline__ void f2_unpack(unsigned long long v, float& lo, float& hi) {
    asm("mov.b64 {%0, %1}, %2;" : "=f"(lo), "=f"(hi) : "l"(v));
}

// ---------------- kernel 0: acc = relu(x @ W0) ----------------
__global__ void k_init(const float* __restrict__ x,
                       const float* __restrict__ W,   // W0: [16][16]
                       float* __restrict__ acc) {
    __shared__ float sW[CH * CH];
    int t = threadIdx.x;
    sW[t] = W[t];
    __syncthreads();

    int row = blockIdx.x * blockDim.x + t;
    const float4* xr4 = reinterpret_cast<const float4*>(x + (size_t)row * CH);
    float xr[CH];
    float4 v0 = xr4[0], v1 = xr4[1], v2 = xr4[2], v3 = xr4[3];
    xr[0]=v0.x; xr[1]=v0.y; xr[2]=v0.z; xr[3]=v0.w;
    xr[4]=v1.x; xr[5]=v1.y; xr[6]=v1.z; xr[7]=v1.w;
    xr[8]=v2.x; xr[9]=v2.y; xr[10]=v2.z; xr[11]=v2.w;
    xr[12]=v3.x; xr[13]=v3.y; xr[14]=v3.z; xr[15]=v3.w;

    float o[CH];
    #pragma unroll
    for (int c = 0; c < CH; c++) o[c] = 0.f;
    #pragma unroll
    for (int j = 0; j < CH; j++) {
        #pragma unroll
        for (int c = 0; c < CH; c++) o[c] += xr[j] * sW[j * CH + c];
    }
    float* ar = acc + (size_t)row * CH;
    #pragma unroll
    for (int c = 0; c < CH; c++) ar[c] = fmaxf(o[c], 0.f);
}

// ---------------- pass kernel ----------------
// 4 warps/CTA: warp = q (k half, bit 1) x s (rowset of 8, bit 0).
// Lane = h*16 + j: half-warps h=0/1 handle interleaved rows 2r+h (r=0..3),
// j strides k (2 floats per lane, 32 k per step). LDG.64 => 2 full 128B lines.
// LDS.128 => 16 unique addrs (2 phases) broadcast across h.
template <bool FINAL>
__global__ __launch_bounds__(THREADS, 4)
void k_pass(const float* __restrict__ L,
            const float* __restrict__ xin,
            float* __restrict__ xout,
            const float* __restrict__ W,      // Wp: [16][16]
            float* __restrict__ acc,
            float* __restrict__ outp) {
    // sxp[q][c2][2*k + e]: pair-major transposed xp chunk, per k-half q
    __shared__ __align__(16) float sxp[2 * 8 * RS];
    __shared__ float sW[CH * CH];

    int t = threadIdx.x;
    sW[t] = W[t];
    sW[t + 128] = W[t + 128];

    int warp = t >> 5;
    int lane = t & 31;
    int q = warp >> 1;          // k half (0: k<4096, 1: k>=4096)
    int s = warp & 1;           // rowset (8 rows)
    int h = lane >> 4;          // row parity within warp
    int j = lane & 15;          // k lane

    int ctarow = blockIdx.x * RPC;
    const float* Lb = L + (size_t)(ctarow + s * 8 + h) * NN + q * (NN / 2);
    const float4* xin4 = reinterpret_cast<const float4*>(xin);

    unsigned long long a2[4][8];
    #pragma unroll
    for (int r = 0; r < 4; r++)
        #pragma unroll
        for (int c2 = 0; c2 < 8; c2++) a2[r][c2] = 0ull;

    for (int i = 0; i < NIT; i++) {
        // ---- stage 256 k per half into pair-major transposed shared ----
        #pragma unroll
        for (int jj = 0; jj < 16; jj++) {
            int idx4 = jj * THREADS + t;          // 0..2047
            int k  = idx4 >> 2;                   // 0..511
            int c4 = idx4 & 3;
            int q0 = k >> 8;                      // which half
            int kl = k & 255;
            int kg = q0 * (NN / 2) + i * KT + kl; // global k row of xin
            float4 v = xin4[(size_t)kg * 4 + c4];
            float* d = sxp + q0 * 8 * RS + 2 * kl;
            *reinterpret_cast<float2*>(d + (2 * c4    ) * RS) = make_float2(v.x, v.y);
            *reinterpret_cast<float2*>(d + (2 * c4 + 1) * RS) = make_float2(v.z, v.w);
        }
        __syncthreads();

        const float* Lc = Lb + i * KT;
        const float* sx = sxp + q * 8 * RS;
        #pragma unroll 4
        for (int it = 0; it < 8; ++it) {          // 8 steps of 32 k
            int kb = it * 32 + 2 * j;
            float2 lv0 = *(const float2*)(Lc + 0 * NN + kb);
            float2 lv1 = *(const float2*)(Lc + 2 * NN + kb);
            float2 lv2 = *(const float2*)(Lc + 4 * NN + kb);
            float2 lv3 = *(const float2*)(Lc + 6 * NN + kb);
            unsigned long long x0 = f2_pack(lv0.x, lv0.x), y0 = f2_pack(lv0.y, lv0.y);
            unsigned long long x1 = f2_pack(lv1.x, lv1.x), y1 = f2_pack(lv1.y, lv1.y);
            unsigned long long x2 = f2_pack(lv2.x, lv2.x), y2 = f2_pack(lv2.y, lv2.y);
            unsigned long long x3 = f2_pack(lv3.x, lv3.x), y3 = f2_pack(lv3.y, lv3.y);
            const float* bp = sx + 2 * kb;
            #pragma unroll
            for (int c2 = 0; c2 < 8; c2++) {
                ulonglong2 qv = *reinterpret_cast<const ulonglong2*>(bp + c2 * RS);
                a2[0][c2] = f2_fma(x0, qv.x, a2[0][c2]);
                a2[0][c2] = f2_fma(y0, qv.y, a2[0][c2]);
                a2[1][c2] = f2_fma(x1, qv.x, a2[1][c2]);
                a2[1][c2] = f2_fma(y1, qv.y, a2[1][c2]);
                a2[2][c2] = f2_fma(x2, qv.x, a2[2][c2]);
                a2[2][c2] = f2_fma(y2, qv.y, a2[2][c2]);
                a2[3][c2] = f2_fma(x3, qv.x, a2[3][c2]);
                a2[3][c2] = f2_fma(y3, qv.y, a2[3][c2]);
            }
        }
        __syncthreads();
    }

    // ---- reduce over j lanes (xor 1,2,4,8 keeps h groups separate) ----
    float y[4][CH];
    #pragma unroll
    for (int r = 0; r < 4; r++) {
        #pragma unroll
        for (int c2 = 0; c2 < 8; c2++) {
            unsigned long long v = a2[r][c2];
            v = f2_add(v, __shfl_xor_sync(0xffffffffu, v, 1, 32));
            v = f2_add(v, __shfl_xor_sync(0xffffffffu, v, 2, 32));
            v = f2_add(v, __shfl_xor_sync(0xffffffffu, v, 4, 32));
            v = f2_add(v, __shfl_xor_sync(0xffffffffu, v, 8, 32));
            f2_unpack(v, y[r][2 * c2], y[r][2 * c2 + 1]);
        }
    }

    // ---- cross-half combine via shared (reuse sxp; synced above) ----
    // red[warp][rowlocal(0..7)*16 + ch]; warp = q*2 + s
    float* red = sxp;
    #pragma unroll
    for (int r = 0; r < 4; r++)
        red[warp * 128 + (2 * r + h) * 16 + j] = y[r][j];
    __syncthreads();

    float* redsum = sxp + 512;
    #pragma unroll
    for (int hh = 0; hh < 2; hh++) {
        int o = t + hh * 128;          // 0..255 = rowlocal*16 + ch
        int rl = o >> 4, c = o & 15;
        int s2 = rl >> 3, rr = rl & 7;
        float ys = red[(0 * 2 + s2) * 128 + rr * 16 + c]
                 + red[(1 * 2 + s2) * 128 + rr * 16 + c];
        redsum[o] = ys;
        if (!FINAL)
            xout[(size_t)(ctarow + rl) * CH + c] = ys;   // raw L^p x
    }
    __syncthreads();

    // ---- tiny GEMM with Wp + relu + accumulate ----
    #pragma unroll
    for (int hh = 0; hh < 2; hh++) {
        int o = t + hh * 128;
        int rl = o >> 4, c = o & 15;
        float sv = 0.f;
        #pragma unroll
        for (int jj = 0; jj < CH; jj++) sv += redsum[rl * 16 + jj] * sW[jj * CH + c];
        sv = fmaxf(sv, 0.f);
        size_t gi = (size_t)(ctarow + rl) * CH + c;
        if (!FINAL) {
            acc[gi] += sv;
        } else {
            outp[gi] = fmaxf(acc[gi] + sv, 0.f);
        }
    }
}

extern "C" void kernel_launch(void* const* d_in, const int* in_sizes, int n_in,
                              void* d_out, int out_size) {
    const float* x = (const float*)d_in[0];   // [8192, 16]
    const float* L = (const float*)d_in[1];   // [8192, 8192]
    const float* W = (const float*)d_in[2];   // [5, 16, 16]
    float* out = (float*)d_out;

    void *p0, *p1, *pa;
    cudaGetSymbolAddress(&p0, g_xbuf0);
    cudaGetSymbolAddress(&p1, g_xbuf1);
    cudaGetSymbolAddress(&pa, g_acc);
    float* xb0 = (float*)p0;
    float* xb1 = (float*)p1;
    float* acc = (float*)pa;

    k_init<<<NN / 256, 256>>>(x, W, acc);                                     // acc = relu(x@W0)
    k_pass<false><<<NCTA, THREADS>>>(L, x,   xb0, W + 1 * 256, acc, nullptr); // p=1
    k_pass<false><<<NCTA, THREADS>>>(L, xb0, xb1, W + 2 * 256, acc, nullptr); // p=2
    k_pass<false><<<NCTA, THREADS>>>(L, xb1, xb0, W + 3 * 256, acc, nullptr); // p=3
    k_pass<true ><<<NCTA, THREADS>>>(L, xb0, nullptr, W + 4 * 256, acc, out); // p=4
}